// round 8
// baseline (speedup 1.0000x reference)
#include <cuda_runtime.h>
#include <cooperative_groups.h>
#include <cstdint>
#include <cstddef>

namespace cg = cooperative_groups;

#define ITERS   50
#define NCAP    200000
#define MCAP    256
#define BLK     512
#define NWARP   (BLK / 32)
#define CLUS    2
// Per-rank survivor capacity: ceil(ceil(200000/128)/32)*16 chunks * 128 = 100352
#define REGION  100352

// Ping-pong survivor INDEX lists, one region per (target, cluster-rank).
__device__ int g_idxA[MCAP][CLUS][REGION];
__device__ int g_idxB[MCAP][CLUS][REGION];

// Repacked pointcloud: {x, y, z, p2}. One LDG.128 per point visit.
__device__ float4 g_p4[NCAP];

__device__ __forceinline__ void argmin_merge(float& bd, int& bi, float d, int i)
{
    if (d < bd || (d == bd && i < bi)) { bd = d; bi = i; }
}

__global__ void prep_kernel(const float* __restrict__ pc, int N)
{
    const int i = blockIdx.x * blockDim.x + threadIdx.x;
    if (i < N) {
        const float x = pc[3 * i], y = pc[3 * i + 1], z = pc[3 * i + 2];
        // p2 = sum(pc*pc, axis=1): plain mul + sequential add (XLA reduce shape)
        const float p2 = __fadd_rn(__fadd_rn(__fmul_rn(x, x), __fmul_rn(y, y)),
                                   __fmul_rn(z, z));
        g_p4[i] = make_float4(x, y, z, p2);
    }
}

__global__ void __cluster_dims__(CLUS, 1, 1) __launch_bounds__(BLK, 3)
cpc_kernel(const float* __restrict__ tg, float* __restrict__ out, int N, int M)
{
    cg::cluster_group cl = cg::this_cluster();
    const int rank = (int)cl.block_rank();
    const int m    = blockIdx.x / CLUS;
    const int tid  = threadIdx.x;
    const int lane = tid & 31;
    const int warp = tid >> 5;

    __shared__ float  s_rd[NWARP];
    __shared__ int    s_ri[NWARP];
    __shared__ float  s_pl[4];      // a0, a1, a2, b
    __shared__ int    s_cursor;
    __shared__ int    s_done;
    __shared__ float2 s_mail[2];    // double-buffered {best_d, best_i bits} mailbox

    const float tx = tg[3 * m + 0];
    const float ty = tg[3 * m + 1];
    const float tz = tg[3 * m + 2];
    // t2 = sum(targets*targets, axis=1): plain mul + sequential add (XLA reduce)
    const float t2 = __fadd_rn(__fadd_rn(__fmul_rn(tx, tx), __fmul_rn(ty, ty)),
                               __fmul_rn(tz, tz));

    float a0 = 0.f, a1 = 0.f, a2 = 0.f, bpl = 0.f;   // current plane
    int   count = N;                                  // elements in my source

    float* outA = out;                                  // [ITERS][M][3]
    float* outB = out + (size_t)ITERS * (size_t)M * 3;  // [ITERS][M]

    for (int iter = 0; iter < ITERS; ++iter) {
        if (tid == 0) { s_cursor = 0; s_done = 0; }
        __syncthreads();

        float bd = __int_as_float(0x7f800000);  // +inf
        int   bi = 0x7fffffff;

        const bool havePlane = (iter >= 1);
        // dst for iter k (k>=1): odd -> B, even -> A. src for k>=2 is the other.
        int* dst = nullptr;
        if (iter >= 1) dst = (iter & 1) ? g_idxB[m][rank] : g_idxA[m][rank];

        if (iter < 2) {
            // Source = raw pointcloud; interleaved chunk stripes across cluster ranks.
            for (int base = (warp + rank * NWARP) * 128; base < count;
                 base += CLUS * NWARP * 128) {
                float4   v[4];
                unsigned kmask[4];
                bool     kp[4];
                int tot = 0;
                // Phase 1: issue ALL loads up front (MLP=4 x LDG.128) — clamped
                // index, no divergent guard, so ptxas can front-batch the LDGs.
                #pragma unroll
                for (int s = 0; s < 4; ++s) {
                    const int i  = base + s * 32 + lane;
                    const int ic = (i < count) ? i : (count - 1);
                    v[s] = g_p4[ic];
                }
                // Phase 2: predicate + ballot + argmin (no memory waits inside).
                #pragma unroll
                for (int s = 0; s < 4; ++s) {
                    const int i = base + s * 32 + lane;
                    bool keep = (i < count);
                    if (keep && havePlane) {
                        const float da = __fmaf_rn(a2, v[s].z,
                                         __fmaf_rn(a1, v[s].y, __fmul_rn(a0, v[s].x)));
                        keep = (__fadd_rn(da, -bpl) < -1e-6f);
                    }
                    kp[s] = keep;
                    kmask[s] = __ballot_sync(0xffffffffu, keep);
                    tot += __popc(kmask[s]);
                    if (keep) {
                        const float dt = __fmaf_rn(tz, v[s].z,
                                         __fmaf_rn(ty, v[s].y, __fmul_rn(tx, v[s].x)));
                        const float d2 = __fadd_rn(__fadd_rn(t2, v[s].w),
                                                   __fmul_rn(-2.f, dt));
                        argmin_merge(bd, bi, d2, i);
                    }
                }
                if (dst) {
                    int wbase = 0;
                    if (lane == 0 && tot) wbase = atomicAdd(&s_cursor, tot);
                    wbase = __shfl_sync(0xffffffffu, wbase, 0);
                    int off = 0;
                    #pragma unroll
                    for (int s = 0; s < 4; ++s) {
                        const unsigned mk = kmask[s];
                        if (kp[s]) {
                            const int pos = wbase + off + __popc(mk & ((1u << lane) - 1u));
                            dst[pos] = base + s * 32 + lane;
                        }
                        off += __popc(mk);
                    }
                }
            }
        } else {
            // Source = my rank's compacted index list from the previous iteration.
            const int* src = (iter & 1) ? g_idxA[m][rank] : g_idxB[m][rank];
            for (int base = warp * 128; base < count; base += NWARP * 128) {
                int      ix[4];
                float4   v[4];
                unsigned kmask[4];
                bool     kp[4];
                bool     vl[4];
                int tot = 0;
                // Phase 1a: load ALL 4 indices first (MLP=4, clamped).
                #pragma unroll
                for (int s = 0; s < 4; ++s) {
                    const int i  = base + s * 32 + lane;
                    vl[s] = (i < count);
                    const int ic = vl[s] ? i : (count - 1);
                    ix[s] = src[ic];
                }
                // Phase 1b: issue ALL 4 point gathers (one LDG.128 each, L2-resident).
                #pragma unroll
                for (int s = 0; s < 4; ++s) v[s] = g_p4[ix[s]];
                // Phase 2: predicate + ballot + argmin.
                #pragma unroll
                for (int s = 0; s < 4; ++s) {
                    bool keep = vl[s];
                    if (keep) {
                        const float da = __fmaf_rn(a2, v[s].z,
                                         __fmaf_rn(a1, v[s].y, __fmul_rn(a0, v[s].x)));
                        keep = (__fadd_rn(da, -bpl) < -1e-6f);
                    }
                    kp[s] = keep;
                    kmask[s] = __ballot_sync(0xffffffffu, keep);
                    tot += __popc(kmask[s]);
                    if (keep) {
                        const float dt = __fmaf_rn(tz, v[s].z,
                                         __fmaf_rn(ty, v[s].y, __fmul_rn(tx, v[s].x)));
                        const float d2 = __fadd_rn(__fadd_rn(t2, v[s].w),
                                                   __fmul_rn(-2.f, dt));
                        argmin_merge(bd, bi, d2, ix[s]);
                    }
                }
                {
                    int wbase = 0;
                    if (lane == 0 && tot) wbase = atomicAdd(&s_cursor, tot);
                    wbase = __shfl_sync(0xffffffffu, wbase, 0);
                    int off = 0;
                    #pragma unroll
                    for (int s = 0; s < 4; ++s) {
                        const unsigned mk = kmask[s];
                        if (kp[s]) {
                            const int pos = wbase + off + __popc(mk & ((1u << lane) - 1u));
                            dst[pos] = ix[s];
                        }
                        off += __popc(mk);
                    }
                }
            }
        }
        __syncthreads();

        // Block argmin reduction (warp shuffle tree, lowest-original-index tie-break)
        #pragma unroll
        for (int o = 16; o; o >>= 1) {
            const float od = __shfl_down_sync(0xffffffffu, bd, o);
            const int   oi = __shfl_down_sync(0xffffffffu, bi, o);
            argmin_merge(bd, bi, od, oi);
        }
        if (lane == 0) { s_rd[warp] = bd; s_ri[warp] = bi; }
        __syncthreads();

        const int buf = iter & 1;
        if (tid < 32) {
            bd = (lane < NWARP) ? s_rd[lane] : __int_as_float(0x7f800000);
            bi = (lane < NWARP) ? s_ri[lane] : 0x7fffffff;
            #pragma unroll
            for (int o = 16; o; o >>= 1) {
                const float od = __shfl_down_sync(0xffffffffu, bd, o);
                const int   oi = __shfl_down_sync(0xffffffffu, bi, o);
                argmin_merge(bd, bi, od, oi);
            }
            if (lane == 0) s_mail[buf] = make_float2(bd, __int_as_float(bi));
        }

        // Cluster-wide exchange of per-rank argmin. barrier.cluster orders the
        // smem write above against the peer's DSMEM read below. Double-buffered
        // mailbox -> a single cluster.sync per iteration is race-free.
        cl.sync();

        if (tid == 0) {
            const float2 ov = s_mail[buf];
            const float2* pmail = cl.map_shared_rank((const float2*)s_mail, rank ^ 1);
            const float2 pv = pmail[buf];
            float fbd = ov.x;  int fbi = __float_as_int(ov.y);
            argmin_merge(fbd, fbi, pv.x, __float_as_int(pv.y));

            const bool empty = (fbi == 0x7fffffff);   // all-inf -> jnp.argmin = 0
            const int  ci = empty ? 0 : fbi;
            const float4 cp = g_p4[ci];
            const float cx = cp.x, cy = cp.y, cz = cp.z;
            const float dx = __fadd_rn(cx, -tx);
            const float dy = __fadd_rn(cy, -ty);
            const float dz = __fadd_rn(cz, -tz);
            const float n2 = __fadd_rn(__fadd_rn(__fmul_rn(dx, dx), __fmul_rn(dy, dy)),
                                       __fmul_rn(dz, dz));
            const float nrm = __fadd_rn(__fsqrt_rn(n2), 1e-8f);
            const float A0 = __fdiv_rn(dx, nrm);
            const float A1 = __fdiv_rn(dy, nrm);
            const float A2 = __fdiv_rn(dz, nrm);
            const float B  = __fadd_rn(__fadd_rn(__fmul_rn(A0, cx), __fmul_rn(A1, cy)),
                                       __fmul_rn(A2, cz));
            if (!empty) {
                if (rank == 0) {
                    const size_t oa = (size_t)iter * M * 3 + (size_t)m * 3;
                    outA[oa + 0] = A0; outA[oa + 1] = A1; outA[oa + 2] = A2;
                    outB[(size_t)iter * M + m] = B;
                }
                s_pl[0] = A0; s_pl[1] = A1; s_pl[2] = A2; s_pl[3] = B;
            } else {
                // Empty survivor set: (a,b) constant for all remaining iterations.
                if (rank == 0) {
                    for (int k = iter; k < ITERS; ++k) {
                        const size_t oa = (size_t)k * M * 3 + (size_t)m * 3;
                        outA[oa + 0] = A0; outA[oa + 1] = A1; outA[oa + 2] = A2;
                        outB[(size_t)k * M + m] = B;
                    }
                }
                s_done = 1;
            }
        }
        __syncthreads();

        if (s_done) break;   // merged state identical on both ranks -> same decision

        a0 = s_pl[0]; a1 = s_pl[1]; a2 = s_pl[2]; bpl = s_pl[3];
        if (iter >= 1) count = s_cursor;
        __syncthreads();   // protect s_cursor / s_done / s_pl against next-iter reset
    }
}

extern "C" void kernel_launch(void* const* d_in, const int* in_sizes, int n_in,
                              void* d_out, int out_size)
{
    const float* pc = (const float*)d_in[0];
    const float* tg = (const float*)d_in[1];
    int szp = in_sizes[0], szt = in_sizes[1];
    if (szp < szt) {  // defensive: pointcloud is the larger input
        const float* t = pc; pc = tg; tg = t;
        int s = szp; szp = szt; szt = s;
    }
    const int N = szp / 3;
    const int M = szt / 3;
    prep_kernel<<<(N + 255) / 256, 256>>>(pc, N);
    cpc_kernel<<<M * CLUS, BLK>>>(tg, (float*)d_out, N, M);
}

// round 15
// speedup vs baseline: 1.2014x; 1.2014x over previous
#include <cuda_runtime.h>
#include <cooperative_groups.h>
#include <cstdint>
#include <cstddef>

namespace cg = cooperative_groups;

#define ITERS   50
#define NCAP    200000
#define MCAP    256
#define BLK     512
#define NWARP   (BLK / 32)
#define CLUS    2
// Per-rank survivor capacity: rank0 gets 784 chunks of the iter-1 scan = 100352
#define REGION  100352

// Ping-pong survivor INDEX lists, one region per (target, cluster-rank).
__device__ int g_idxA[MCAP][CLUS][REGION];
__device__ int g_idxB[MCAP][CLUS][REGION];

// Repacked pointcloud: {x, y, z, p2}. One LDG.128 per point visit.
__device__ float4 g_p4[NCAP];

__device__ __forceinline__ void argmin_merge(float& bd, int& bi, float d, int i)
{
    if (d < bd || (d == bd && i < bi)) { bd = d; bi = i; }
}

__global__ void prep_kernel(const float* __restrict__ pc, int N)
{
    const int i = blockIdx.x * blockDim.x + threadIdx.x;
    if (i < N) {
        const float x = pc[3 * i], y = pc[3 * i + 1], z = pc[3 * i + 2];
        // p2 = sum(pc*pc, axis=1): plain mul + sequential add (XLA reduce shape)
        const float p2 = __fadd_rn(__fadd_rn(__fmul_rn(x, x), __fmul_rn(y, y)),
                                   __fmul_rn(z, z));
        g_p4[i] = make_float4(x, y, z, p2);
    }
}

__global__ void __cluster_dims__(CLUS, 1, 1) __launch_bounds__(BLK, 3)
cpc_kernel(const float* __restrict__ tg, float* __restrict__ out, int N, int M)
{
    cg::cluster_group cl = cg::this_cluster();
    const int rank = (int)cl.block_rank();
    const int m    = blockIdx.x / CLUS;
    const int tid  = threadIdx.x;
    const int lane = tid & 31;
    const int warp = tid >> 5;

    __shared__ float  s_rd[NWARP];
    __shared__ int    s_ri[NWARP];
    __shared__ float  s_pl[4];      // a0, a1, a2, b
    __shared__ int    s_cursor;
    __shared__ int    s_done;
    __shared__ float2 s_mail[2];    // double-buffered {best_d, best_i bits} mailbox

    const float tx = tg[3 * m + 0];
    const float ty = tg[3 * m + 1];
    const float tz = tg[3 * m + 2];
    // t2 = sum(targets*targets, axis=1): plain mul + sequential add (XLA reduce)
    const float t2 = __fadd_rn(__fadd_rn(__fmul_rn(tx, tx), __fmul_rn(ty, ty)),
                               __fmul_rn(tz, tz));

    float a0 = 0.f, a1 = 0.f, a2 = 0.f, bpl = 0.f;   // current plane
    int   count = N;                                  // elements in my source

    float* outA = out;                                  // [ITERS][M][3]
    float* outB = out + (size_t)ITERS * (size_t)M * 3;  // [ITERS][M]

    for (int iter = 0; iter < ITERS; ++iter) {
        if (tid == 0) { s_cursor = 0; s_done = 0; }
        __syncthreads();

        float bd = __int_as_float(0x7f800000);  // +inf
        int   bi = 0x7fffffff;

        // dst for iter k (k>=1): odd -> B, even -> A. src for k>=2 is the other.
        int* dst = nullptr;
        if (iter >= 1) dst = (iter & 1) ? g_idxB[m][rank] : g_idxA[m][rank];

        if (iter == 0) {
            // Pure argmin over the pointcloud — no plane yet, no compaction:
            // no ballot/popc/predicate at all. Clamped loads, guarded merge.
            for (int base = (warp + rank * NWARP) * 128; base < count;
                 base += CLUS * NWARP * 128) {
                float4 v[4];
                #pragma unroll
                for (int s = 0; s < 4; ++s) {
                    const int i  = base + s * 32 + lane;
                    const int ic = (i < count) ? i : (count - 1);
                    v[s] = g_p4[ic];
                }
                #pragma unroll
                for (int s = 0; s < 4; ++s) {
                    const int i = base + s * 32 + lane;
                    if (i < count) {
                        const float dt = __fmaf_rn(tz, v[s].z,
                                         __fmaf_rn(ty, v[s].y, __fmul_rn(tx, v[s].x)));
                        const float d2 = __fadd_rn(__fadd_rn(t2, v[s].w),
                                                   __fmul_rn(-2.f, dt));
                        argmin_merge(bd, bi, d2, i);
                    }
                }
            }
        } else if (iter == 1) {
            // Predicate + argmin + compaction over the raw pointcloud.
            for (int base = (warp + rank * NWARP) * 128; base < count;
                 base += CLUS * NWARP * 128) {
                float4   v[4];
                unsigned kmask[4];
                bool     kp[4];
                int tot = 0;
                #pragma unroll
                for (int s = 0; s < 4; ++s) {
                    const int i  = base + s * 32 + lane;
                    const int ic = (i < count) ? i : (count - 1);
                    v[s] = g_p4[ic];
                }
                #pragma unroll
                for (int s = 0; s < 4; ++s) {
                    const int i = base + s * 32 + lane;
                    bool keep = (i < count);
                    if (keep) {
                        const float da = __fmaf_rn(a2, v[s].z,
                                         __fmaf_rn(a1, v[s].y, __fmul_rn(a0, v[s].x)));
                        keep = (__fadd_rn(da, -bpl) < -1e-6f);
                    }
                    kp[s] = keep;
                    kmask[s] = __ballot_sync(0xffffffffu, keep);
                    tot += __popc(kmask[s]);
                    if (keep) {
                        const float dt = __fmaf_rn(tz, v[s].z,
                                         __fmaf_rn(ty, v[s].y, __fmul_rn(tx, v[s].x)));
                        const float d2 = __fadd_rn(__fadd_rn(t2, v[s].w),
                                                   __fmul_rn(-2.f, dt));
                        argmin_merge(bd, bi, d2, i);
                    }
                }
                int wbase = 0;
                if (lane == 0 && tot) wbase = atomicAdd(&s_cursor, tot);
                wbase = __shfl_sync(0xffffffffu, wbase, 0);
                int off = 0;
                #pragma unroll
                for (int s = 0; s < 4; ++s) {
                    const unsigned mk = kmask[s];
                    if (kp[s]) {
                        const int pos = wbase + off + __popc(mk & ((1u << lane) - 1u));
                        dst[pos] = base + s * 32 + lane;
                    }
                    off += __popc(mk);
                }
            }
        } else {
            // Source = my rank's compacted index list from the previous iteration.
            const int* src = (iter & 1) ? g_idxA[m][rank] : g_idxB[m][rank];
            for (int base = warp * 128; base < count; base += NWARP * 128) {
                int      ix[4];
                float4   v[4];
                unsigned kmask[4];
                bool     kp[4];
                bool     vl[4];
                int tot = 0;
                // Phase 1a: load ALL 4 indices first (MLP=4, clamped).
                #pragma unroll
                for (int s = 0; s < 4; ++s) {
                    const int i  = base + s * 32 + lane;
                    vl[s] = (i < count);
                    const int ic = vl[s] ? i : (count - 1);
                    ix[s] = src[ic];
                }
                // Phase 1b: issue ALL 4 point gathers (one LDG.128 each, L2-resident).
                #pragma unroll
                for (int s = 0; s < 4; ++s) v[s] = g_p4[ix[s]];
                // Phase 2: predicate + ballot + argmin.
                #pragma unroll
                for (int s = 0; s < 4; ++s) {
                    bool keep = vl[s];
                    if (keep) {
                        const float da = __fmaf_rn(a2, v[s].z,
                                         __fmaf_rn(a1, v[s].y, __fmul_rn(a0, v[s].x)));
                        keep = (__fadd_rn(da, -bpl) < -1e-6f);
                    }
                    kp[s] = keep;
                    kmask[s] = __ballot_sync(0xffffffffu, keep);
                    tot += __popc(kmask[s]);
                    if (keep) {
                        const float dt = __fmaf_rn(tz, v[s].z,
                                         __fmaf_rn(ty, v[s].y, __fmul_rn(tx, v[s].x)));
                        const float d2 = __fadd_rn(__fadd_rn(t2, v[s].w),
                                                   __fmul_rn(-2.f, dt));
                        argmin_merge(bd, bi, d2, ix[s]);
                    }
                }
                int wbase = 0;
                if (lane == 0 && tot) wbase = atomicAdd(&s_cursor, tot);
                wbase = __shfl_sync(0xffffffffu, wbase, 0);
                int off = 0;
                #pragma unroll
                for (int s = 0; s < 4; ++s) {
                    const unsigned mk = kmask[s];
                    if (kp[s]) {
                        const int pos = wbase + off + __popc(mk & ((1u << lane) - 1u));
                        dst[pos] = ix[s];
                    }
                    off += __popc(mk);
                }
            }
        }
        __syncthreads();   // compaction writes + s_cursor final

        // Block argmin reduction (warp shuffle tree, lowest-original-index tie-break)
        #pragma unroll
        for (int o = 16; o; o >>= 1) {
            const float od = __shfl_down_sync(0xffffffffu, bd, o);
            const int   oi = __shfl_down_sync(0xffffffffu, bi, o);
            argmin_merge(bd, bi, od, oi);
        }
        if (lane == 0) { s_rd[warp] = bd; s_ri[warp] = bi; }
        __syncthreads();

        const int buf = iter & 1;
        if (tid < 32) {
            bd = (lane < NWARP) ? s_rd[lane] : __int_as_float(0x7f800000);
            bi = (lane < NWARP) ? s_ri[lane] : 0x7fffffff;
            #pragma unroll
            for (int o = 16; o; o >>= 1) {
                const float od = __shfl_down_sync(0xffffffffu, bd, o);
                const int   oi = __shfl_down_sync(0xffffffffu, bi, o);
                argmin_merge(bd, bi, od, oi);
            }
            if (lane == 0) s_mail[buf] = make_float2(bd, __int_as_float(bi));
        }

        // Cluster-wide exchange of per-rank argmin. Double-buffered mailbox ->
        // a single cluster.sync per iteration is race-free.
        cl.sync();

        if (tid == 0) {
            const float2 ov = s_mail[buf];
            const float2* pmail = cl.map_shared_rank((const float2*)s_mail, rank ^ 1);
            const float2 pv = pmail[buf];
            float fbd = ov.x;  int fbi = __float_as_int(ov.y);
            argmin_merge(fbd, fbi, pv.x, __float_as_int(pv.y));

            const bool empty = (fbi == 0x7fffffff);   // all-inf -> jnp.argmin = 0
            const int  ci = empty ? 0 : fbi;
            const float4 cp = g_p4[ci];
            const float cx = cp.x, cy = cp.y, cz = cp.z;
            const float dx = __fadd_rn(cx, -tx);
            const float dy = __fadd_rn(cy, -ty);
            const float dz = __fadd_rn(cz, -tz);
            const float n2 = __fadd_rn(__fadd_rn(__fmul_rn(dx, dx), __fmul_rn(dy, dy)),
                                       __fmul_rn(dz, dz));
            const float nrm = __fadd_rn(__fsqrt_rn(n2), 1e-8f);
            const float A0 = __fdiv_rn(dx, nrm);
            const float A1 = __fdiv_rn(dy, nrm);
            const float A2 = __fdiv_rn(dz, nrm);
            const float B  = __fadd_rn(__fadd_rn(__fmul_rn(A0, cx), __fmul_rn(A1, cy)),
                                       __fmul_rn(A2, cz));
            if (!empty) {
                if (rank == 0) {
                    const size_t oa = (size_t)iter * M * 3 + (size_t)m * 3;
                    outA[oa + 0] = A0; outA[oa + 1] = A1; outA[oa + 2] = A2;
                    outB[(size_t)iter * M + m] = B;
                }
                s_pl[0] = A0; s_pl[1] = A1; s_pl[2] = A2; s_pl[3] = B;
            } else {
                // Empty survivor set: (a,b) constant for all remaining iterations.
                if (rank == 0) {
                    for (int k = iter; k < ITERS; ++k) {
                        const size_t oa = (size_t)k * M * 3 + (size_t)m * 3;
                        outA[oa + 0] = A0; outA[oa + 1] = A1; outA[oa + 2] = A2;
                        outB[(size_t)k * M + m] = B;
                    }
                }
                s_done = 1;
            }
        }
        __syncthreads();

        if (s_done) break;   // merged state identical on both ranks -> same decision

        a0 = s_pl[0]; a1 = s_pl[1]; a2 = s_pl[2]; bpl = s_pl[3];
        if (iter >= 1) count = s_cursor;
        __syncthreads();   // protect s_cursor / s_done / s_pl against next-iter reset
    }

    // Exit barrier: no CTA may leave while its peer might still be reading this
    // CTA's s_mail via DSMEM (both ranks provably exit the loop at the same
    // iteration, so all cluster threads reach this sync exactly once).
    cl.sync();
}

extern "C" void kernel_launch(void* const* d_in, const int* in_sizes, int n_in,
                              void* d_out, int out_size)
{
    const float* pc = (const float*)d_in[0];
    const float* tg = (const float*)d_in[1];
    int szp = in_sizes[0], szt = in_sizes[1];
    if (szp < szt) {  // defensive: pointcloud is the larger input
        const float* t = pc; pc = tg; tg = t;
        int s = szp; szp = szt; szt = s;
    }
    const int N = szp / 3;
    const int M = szt / 3;
    prep_kernel<<<(N + 255) / 256, 256>>>(pc, N);
    cpc_kernel<<<M * CLUS, BLK>>>(tg, (float*)d_out, N, M);
}

// round 17
// speedup vs baseline: 1.2438x; 1.0353x over previous
#include <cuda_runtime.h>
#include <cooperative_groups.h>
#include <cstdint>
#include <cstddef>

namespace cg = cooperative_groups;

#define ITERS   50
#define NCAP    200000
#define MCAP    256
#define BLK     512
#define NWARP   (BLK / 32)
#define CLUS    2
// Per-rank survivor capacity: rank0 gets 784 chunks of the iter-1 scan = 100352
#define REGION  100352

#define F_INF   __int_as_float(0x7f800000)
#define I_SENT  0x7fffffff

// Ping-pong survivor INDEX lists, one region per (target, cluster-rank).
__device__ int g_idxA[MCAP][CLUS][REGION];
__device__ int g_idxB[MCAP][CLUS][REGION];

// Repacked pointcloud: {x, y, z, p2}. One LDG.128 per point visit.
__device__ float4 g_p4[NCAP];

__device__ __forceinline__ void argmin_merge(float& bd, int& bi, float d, int i)
{
    if (d < bd || (d == bd && i < bi)) { bd = d; bi = i; }
}

__global__ void prep_kernel(const float* __restrict__ pc, int N)
{
    const int i = blockIdx.x * blockDim.x + threadIdx.x;
    if (i < N) {
        const float x = pc[3 * i], y = pc[3 * i + 1], z = pc[3 * i + 2];
        // p2 = sum(pc*pc, axis=1): plain mul + sequential add (XLA reduce shape)
        const float p2 = __fadd_rn(__fadd_rn(__fmul_rn(x, x), __fmul_rn(y, y)),
                                   __fmul_rn(z, z));
        g_p4[i] = make_float4(x, y, z, p2);
    }
}

__global__ void __cluster_dims__(CLUS, 1, 1) __launch_bounds__(BLK, 3)
cpc_kernel(const float* __restrict__ tg, float* __restrict__ out, int N, int M)
{
    cg::cluster_group cl = cg::this_cluster();
    const int rank = (int)cl.block_rank();
    const int m    = blockIdx.x / CLUS;
    const int tid  = threadIdx.x;
    const int lane = tid & 31;
    const int warp = tid >> 5;

    __shared__ float  s_rd[NWARP];
    __shared__ int    s_ri[NWARP];
    __shared__ float  s_pl[4];      // a0, a1, a2, b
    __shared__ int    s_cursor;
    __shared__ int    s_done;
    __shared__ float2 s_mail[2];    // double-buffered {best_d, best_i bits} mailbox

    const float tx = tg[3 * m + 0];
    const float ty = tg[3 * m + 1];
    const float tz = tg[3 * m + 2];
    // t2 = sum(targets*targets, axis=1): plain mul + sequential add (XLA reduce)
    const float t2 = __fadd_rn(__fadd_rn(__fmul_rn(tx, tx), __fmul_rn(ty, ty)),
                               __fmul_rn(tz, tz));

    float a0 = 0.f, a1 = 0.f, a2 = 0.f, bpl = 0.f;   // current plane
    int   count = N;                                  // elements in my source

    float* outA = out;                                  // [ITERS][M][3]
    float* outB = out + (size_t)ITERS * (size_t)M * 3;  // [ITERS][M]

    for (int iter = 0; iter < ITERS; ++iter) {
        if (tid == 0) { s_cursor = 0; s_done = 0; }
        __syncthreads();

        float bd = F_INF;
        int   bi = I_SENT;

        // dst for iter k (k>=1): odd -> B, even -> A. src for k>=2 is the other.
        int* dst = nullptr;
        if (iter >= 1) dst = (iter & 1) ? g_idxB[m][rank] : g_idxA[m][rank];

        if (iter == 0) {
            // Pure argmin over the pointcloud — no plane yet, no compaction,
            // and fully branch-free (select-inf merge for OOB lanes).
            for (int base = (warp + rank * NWARP) * 128; base < count;
                 base += CLUS * NWARP * 128) {
                float4 v[4];
                #pragma unroll
                for (int s = 0; s < 4; ++s) {
                    const int i  = base + s * 32 + lane;
                    const int ic = (i < count) ? i : (count - 1);
                    v[s] = g_p4[ic];
                }
                #pragma unroll
                for (int s = 0; s < 4; ++s) {
                    const int i = base + s * 32 + lane;
                    const bool ok = (i < count);
                    const float dt = __fmaf_rn(tz, v[s].z,
                                     __fmaf_rn(ty, v[s].y, __fmul_rn(tx, v[s].x)));
                    const float d2 = __fadd_rn(__fadd_rn(t2, v[s].w),
                                               __fmul_rn(-2.f, dt));
                    const float d2k = ok ? d2 : F_INF;
                    const int   ik  = ok ? i  : I_SENT;
                    argmin_merge(bd, bi, d2k, ik);
                }
            }
        } else if (iter == 1) {
            // Predicate + argmin + compaction over the raw pointcloud.
            // Branch-free merge: rejected lanes contribute (inf, sentinel).
            for (int base = (warp + rank * NWARP) * 128; base < count;
                 base += CLUS * NWARP * 128) {
                float4   v[4];
                unsigned kmask[4];
                bool     kp[4];
                int tot = 0;
                #pragma unroll
                for (int s = 0; s < 4; ++s) {
                    const int i  = base + s * 32 + lane;
                    const int ic = (i < count) ? i : (count - 1);
                    v[s] = g_p4[ic];
                }
                #pragma unroll
                for (int s = 0; s < 4; ++s) {
                    const int i = base + s * 32 + lane;
                    const float da = __fmaf_rn(a2, v[s].z,
                                     __fmaf_rn(a1, v[s].y, __fmul_rn(a0, v[s].x)));
                    const bool keep = (i < count) &&
                                      (__fadd_rn(da, -bpl) < -1e-6f);
                    kp[s] = keep;
                    kmask[s] = __ballot_sync(0xffffffffu, keep);
                    tot += __popc(kmask[s]);
                    const float dt = __fmaf_rn(tz, v[s].z,
                                     __fmaf_rn(ty, v[s].y, __fmul_rn(tx, v[s].x)));
                    const float d2 = __fadd_rn(__fadd_rn(t2, v[s].w),
                                               __fmul_rn(-2.f, dt));
                    const float d2k = keep ? d2 : F_INF;
                    const int   ik  = keep ? i  : I_SENT;
                    argmin_merge(bd, bi, d2k, ik);
                }
                int wbase = 0;
                if (lane == 0 && tot) wbase = atomicAdd(&s_cursor, tot);
                wbase = __shfl_sync(0xffffffffu, wbase, 0);
                int off = 0;
                #pragma unroll
                for (int s = 0; s < 4; ++s) {
                    const unsigned mk = kmask[s];
                    if (kp[s]) {
                        const int pos = wbase + off + __popc(mk & ((1u << lane) - 1u));
                        dst[pos] = base + s * 32 + lane;
                    }
                    off += __popc(mk);
                }
            }
        } else {
            // Source = my rank's compacted index list from the previous iteration.
            const int* src = (iter & 1) ? g_idxA[m][rank] : g_idxB[m][rank];
            for (int base = warp * 128; base < count; base += NWARP * 128) {
                int      ix[4];
                float4   v[4];
                unsigned kmask[4];
                bool     kp[4];
                bool     vl[4];
                int tot = 0;
                // Phase 1a: load ALL 4 indices first (MLP=4, clamped).
                #pragma unroll
                for (int s = 0; s < 4; ++s) {
                    const int i  = base + s * 32 + lane;
                    vl[s] = (i < count);
                    const int ic = vl[s] ? i : (count - 1);
                    ix[s] = src[ic];
                }
                // Phase 1b: issue ALL 4 point gathers (one LDG.128 each, L2-resident).
                #pragma unroll
                for (int s = 0; s < 4; ++s) v[s] = g_p4[ix[s]];
                // Phase 2: predicate + ballot + branch-free argmin.
                #pragma unroll
                for (int s = 0; s < 4; ++s) {
                    const float da = __fmaf_rn(a2, v[s].z,
                                     __fmaf_rn(a1, v[s].y, __fmul_rn(a0, v[s].x)));
                    const bool keep = vl[s] &&
                                      (__fadd_rn(da, -bpl) < -1e-6f);
                    kp[s] = keep;
                    kmask[s] = __ballot_sync(0xffffffffu, keep);
                    tot += __popc(kmask[s]);
                    const float dt = __fmaf_rn(tz, v[s].z,
                                     __fmaf_rn(ty, v[s].y, __fmul_rn(tx, v[s].x)));
                    const float d2 = __fadd_rn(__fadd_rn(t2, v[s].w),
                                               __fmul_rn(-2.f, dt));
                    const float d2k = keep ? d2   : F_INF;
                    const int   ik  = keep ? ix[s] : I_SENT;
                    argmin_merge(bd, bi, d2k, ik);
                }
                int wbase = 0;
                if (lane == 0 && tot) wbase = atomicAdd(&s_cursor, tot);
                wbase = __shfl_sync(0xffffffffu, wbase, 0);
                int off = 0;
                #pragma unroll
                for (int s = 0; s < 4; ++s) {
                    const unsigned mk = kmask[s];
                    if (kp[s]) {
                        const int pos = wbase + off + __popc(mk & ((1u << lane) - 1u));
                        dst[pos] = ix[s];
                    }
                    off += __popc(mk);
                }
            }
        }
        __syncthreads();   // compaction writes + s_cursor final

        // Block argmin reduction (warp shuffle tree, lowest-original-index tie-break)
        #pragma unroll
        for (int o = 16; o; o >>= 1) {
            const float od = __shfl_down_sync(0xffffffffu, bd, o);
            const int   oi = __shfl_down_sync(0xffffffffu, bi, o);
            argmin_merge(bd, bi, od, oi);
        }
        if (lane == 0) { s_rd[warp] = bd; s_ri[warp] = bi; }
        __syncthreads();

        const int buf = iter & 1;
        if (tid < 32) {
            bd = (lane < NWARP) ? s_rd[lane] : F_INF;
            bi = (lane < NWARP) ? s_ri[lane] : I_SENT;
            #pragma unroll
            for (int o = 16; o; o >>= 1) {
                const float od = __shfl_down_sync(0xffffffffu, bd, o);
                const int   oi = __shfl_down_sync(0xffffffffu, bi, o);
                argmin_merge(bd, bi, od, oi);
            }
            if (lane == 0) s_mail[buf] = make_float2(bd, __int_as_float(bi));
        }

        // Cluster-wide exchange of per-rank argmin. Double-buffered mailbox ->
        // a single cluster.sync per iteration is race-free.
        cl.sync();

        if (tid == 0) {
            const float2 ov = s_mail[buf];
            const float2* pmail = cl.map_shared_rank((const float2*)s_mail, rank ^ 1);
            const float2 pv = pmail[buf];
            float fbd = ov.x;  int fbi = __float_as_int(ov.y);
            argmin_merge(fbd, fbi, pv.x, __float_as_int(pv.y));

            const bool empty = (fbi == I_SENT);       // all-inf -> jnp.argmin = 0
            const int  ci = empty ? 0 : fbi;
            const float4 cp = g_p4[ci];
            const float cx = cp.x, cy = cp.y, cz = cp.z;
            const float dx = __fadd_rn(cx, -tx);
            const float dy = __fadd_rn(cy, -ty);
            const float dz = __fadd_rn(cz, -tz);
            const float n2 = __fadd_rn(__fadd_rn(__fmul_rn(dx, dx), __fmul_rn(dy, dy)),
                                       __fmul_rn(dz, dz));
            const float nrm = __fadd_rn(__fsqrt_rn(n2), 1e-8f);
            const float A0 = __fdiv_rn(dx, nrm);
            const float A1 = __fdiv_rn(dy, nrm);
            const float A2 = __fdiv_rn(dz, nrm);
            const float B  = __fadd_rn(__fadd_rn(__fmul_rn(A0, cx), __fmul_rn(A1, cy)),
                                       __fmul_rn(A2, cz));
            if (!empty) {
                if (rank == 0) {
                    const size_t oa = (size_t)iter * M * 3 + (size_t)m * 3;
                    outA[oa + 0] = A0; outA[oa + 1] = A1; outA[oa + 2] = A2;
                    outB[(size_t)iter * M + m] = B;
                }
                s_pl[0] = A0; s_pl[1] = A1; s_pl[2] = A2; s_pl[3] = B;
            } else {
                // Empty survivor set: (a,b) constant for all remaining iterations.
                if (rank == 0) {
                    for (int k = iter; k < ITERS; ++k) {
                        const size_t oa = (size_t)k * M * 3 + (size_t)m * 3;
                        outA[oa + 0] = A0; outA[oa + 1] = A1; outA[oa + 2] = A2;
                        outB[(size_t)k * M + m] = B;
                    }
                }
                s_done = 1;
            }
        }
        __syncthreads();

        if (s_done) break;   // merged state identical on both ranks -> same decision

        a0 = s_pl[0]; a1 = s_pl[1]; a2 = s_pl[2]; bpl = s_pl[3];
        if (iter >= 1) count = s_cursor;
        __syncthreads();   // protect s_cursor / s_done / s_pl against next-iter reset
    }

    // Exit barrier: no CTA may leave while its peer might still be reading this
    // CTA's s_mail via DSMEM (both ranks provably exit the loop at the same
    // iteration, so all cluster threads reach this sync exactly once).
    cl.sync();
}

extern "C" void kernel_launch(void* const* d_in, const int* in_sizes, int n_in,
                              void* d_out, int out_size)
{
    const float* pc = (const float*)d_in[0];
    const float* tg = (const float*)d_in[1];
    int szp = in_sizes[0], szt = in_sizes[1];
    if (szp < szt) {  // defensive: pointcloud is the larger input
        const float* t = pc; pc = tg; tg = t;
        int s = szp; szp = szt; szt = s;
    }
    const int N = szp / 3;
    const int M = szt / 3;
    prep_kernel<<<(N + 255) / 256, 256>>>(pc, N);
    cpc_kernel<<<M * CLUS, BLK>>>(tg, (float*)d_out, N, M);
}